// round 12
// baseline (speedup 1.0000x reference)
#include <cuda_runtime.h>
#include <cuda_bf16.h>
#include <math.h>
#include <stdint.h>

// ----------------------------------------------------------------------------
// TransformerLayer: B=2, L=2048, D=1024, H=16, HD=64, FF=4096
// bf16x3 split-precision tensor-core pipeline. Weights pre-split+pre-transposed
// (n-major pair-packed). GEMM mainloop: cp.async + ldmatrix.x4 + HMMA only.
// R10 fix: split_wt smem tile stride 17 -> 20 (uint4 alignment).
// ----------------------------------------------------------------------------

#define NTOK   4096
#define DMODEL 1024
#define NHEAD  16
#define HDIM   64
#define FFDIM  4096
#define SEQ    2048

// Weight split offsets (u32 pair units). Layout: Wt[n][K/2] (n-major).
#define OFF_WQKV 0
#define OFF_WOUT (512 * 3072)
#define OFF_W1   (OFF_WOUT + 512 * 1024)
#define OFF_W2   (OFF_W1 + 512 * 8192)
#define WTOT     (OFF_W2 + 2048 * 1024)

__device__ uint32_t g_wh[WTOT];
__device__ uint32_t g_wl[WTOT];
__device__ uint32_t g_ah[(size_t)NTOK * 2048];   // activation A (pair-packed)
__device__ uint32_t g_al[(size_t)NTOK * 2048];
__device__ uint32_t g_qh[(size_t)NTOK * 1536];   // qkv (pair-packed, Q pre-scaled)
__device__ uint32_t g_ql[(size_t)NTOK * 1536];
__device__ float    g_u [(size_t)NTOK * 2 * FFDIM];
__device__ float    g_p [(size_t)NTOK * DMODEL];

// ---------------------------------------------------------------------------
__device__ __forceinline__ void split2(float x, float y,
                                       uint32_t& hi, uint32_t& lo) {
    __nv_bfloat162 h = __floats2bfloat162_rn(x, y);
    float lx = x - __bfloat162float(h.x);
    float ly = y - __bfloat162float(h.y);
    __nv_bfloat162 l = __floats2bfloat162_rn(lx, ly);
    hi = *(uint32_t*)&h;
    lo = *(uint32_t*)&l;
}

__device__ __forceinline__ void mma_bf16(float c[4], const uint32_t a[4],
                                         uint32_t b0, uint32_t b1) {
    asm volatile(
        "mma.sync.aligned.m16n8k16.row.col.f32.bf16.bf16.f32 "
        "{%0,%1,%2,%3}, {%4,%5,%6,%7}, {%8,%9}, {%0,%1,%2,%3};"
        : "+f"(c[0]), "+f"(c[1]), "+f"(c[2]), "+f"(c[3])
        : "r"(a[0]), "r"(a[1]), "r"(a[2]), "r"(a[3]), "r"(b0), "r"(b1));
}

__device__ __forceinline__ void ldsm4(uint32_t& r0, uint32_t& r1,
                                      uint32_t& r2, uint32_t& r3,
                                      uint32_t addr) {
    asm volatile("ldmatrix.sync.aligned.m8n8.x4.shared.b16 {%0,%1,%2,%3}, [%4];"
                 : "=r"(r0), "=r"(r1), "=r"(r2), "=r"(r3) : "r"(addr));
}

#define CP16(smem_u32_addr, gptr) \
    asm volatile("cp.async.cg.shared.global [%0], [%1], 16;" \
                 :: "r"(smem_u32_addr), "l"(gptr))
#define CP_COMMIT() asm volatile("cp.async.commit_group;")
#define CP_WAIT1()  asm volatile("cp.async.wait_group 1;")
#define CP_WAIT0()  asm volatile("cp.async.wait_group 0;")

// ---------------------------------------------------------------------------
// Weight split + transpose: W[K,N] fp32 -> Wt hi/lo [N][K/2] u32 pair-packed.
// Tile 32k x 64n through smem; fully coalesced both sides.
// Grid: (N/64, K/32), block 256.  Smem row stride 20 (80B) for uint4 alignment.
// ---------------------------------------------------------------------------
__global__ __launch_bounds__(256) void split_wt_kernel(
    const float* __restrict__ W, uint32_t* __restrict__ Wh,
    uint32_t* __restrict__ Wl, int N, int Khalf)
{
    __shared__ uint32_t Sh[64][20];
    __shared__ uint32_t Sl[64][20];
    const int n0  = blockIdx.x * 64;
    const int kp0 = blockIdx.y * 16;
    const int t = threadIdx.x;
    {
        int kp = t >> 4;              // 0..15
        int n4 = (t & 15) * 4;
        const float* W0 = W + (size_t)(2 * (kp0 + kp)) * N + n0 + n4;
        float4 r0 = *(const float4*)(W0);
        float4 r1 = *(const float4*)(W0 + N);
        uint32_t h, l;
        split2(r0.x, r1.x, h, l); Sh[n4+0][kp] = h; Sl[n4+0][kp] = l;
        split2(r0.y, r1.y, h, l); Sh[n4+1][kp] = h; Sl[n4+1][kp] = l;
        split2(r0.z, r1.z, h, l); Sh[n4+2][kp] = h; Sl[n4+2][kp] = l;
        split2(r0.w, r1.w, h, l); Sh[n4+3][kp] = h; Sl[n4+3][kp] = l;
    }
    __syncthreads();
    {
        int n  = t >> 2;              // 0..63
        int kq = (t & 3) * 4;
        size_t off = (size_t)(n0 + n) * Khalf + kp0 + kq;
        *(uint4*)(Wh + off) = *(uint4*)&Sh[n][kq];
        *(uint4*)(Wl + off) = *(uint4*)&Sl[n][kq];
    }
}

// ---------------------------------------------------------------------------
__device__ __forceinline__ float2 block_reduce2_256(float a, float b) {
    #pragma unroll
    for (int o = 16; o > 0; o >>= 1) {
        a += __shfl_xor_sync(0xffffffffu, a, o);
        b += __shfl_xor_sync(0xffffffffu, b, o);
    }
    __shared__ float sa[8], sb[8];
    int w = threadIdx.x >> 5, lane = threadIdx.x & 31;
    __syncthreads();
    if (lane == 0) { sa[w] = a; sb[w] = b; }
    __syncthreads();
    float ta = 0.f, tb = 0.f;
    #pragma unroll
    for (int i = 0; i < 8; i++) { ta += sa[i]; tb += sb[i]; }
    return make_float2(ta, tb);
}

// LayerNorm -> pair-packed hi/lo output (row stride 512 pairs)
__global__ __launch_bounds__(256) void ln_kernel(
    const float* __restrict__ in, const float* __restrict__ g,
    const float* __restrict__ b,
    uint32_t* __restrict__ outH, uint32_t* __restrict__ outL)
{
    int row = blockIdx.x;
    int t = threadIdx.x;
    const float4 v = ((const float4*)(in + (size_t)row * DMODEL))[t];
    float s = v.x + v.y + v.z + v.w;
    float q = v.x*v.x + v.y*v.y + v.z*v.z + v.w*v.w;
    float2 r = block_reduce2_256(s, q);
    const float inv_n = 1.0f / DMODEL;
    float mu  = r.x * inv_n;
    float var = r.y * inv_n - mu * mu;
    float inv = rsqrtf(var + 1e-5f);
    const float4 gg = ((const float4*)g)[t];
    const float4 bb = ((const float4*)b)[t];
    float o0 = (v.x - mu) * inv * gg.x + bb.x;
    float o1 = (v.y - mu) * inv * gg.y + bb.y;
    float o2 = (v.z - mu) * inv * gg.z + bb.z;
    float o3 = (v.w - mu) * inv * gg.w + bb.w;
    uint32_t h0,l0,h1,l1;
    split2(o0, o1, h0, l0);
    split2(o2, o3, h1, l1);
    ((uint2*)(outH + (size_t)row * 512))[t] = make_uint2(h0, h1);
    ((uint2*)(outL + (size_t)row * 512))[t] = make_uint2(l0, l1);
}

// Fused LN_inner -> *scale -> LN_pre_ff -> pair-packed output
__global__ __launch_bounds__(256) void dln_kernel(
    const float* __restrict__ in,
    const float* __restrict__ g1, const float* __restrict__ b1,
    const float* __restrict__ sc,
    const float* __restrict__ g2, const float* __restrict__ b2,
    uint32_t* __restrict__ outH, uint32_t* __restrict__ outL)
{
    int row = blockIdx.x;
    int t = threadIdx.x;
    const float inv_n = 1.0f / DMODEL;
    const float4 v = ((const float4*)(in + (size_t)row * DMODEL))[t];
    float s = v.x + v.y + v.z + v.w;
    float q = v.x*v.x + v.y*v.y + v.z*v.z + v.w*v.w;
    float2 r = block_reduce2_256(s, q);
    float mu  = r.x * inv_n;
    float var = r.y * inv_n - mu * mu;
    float inv = rsqrtf(var + 1e-5f);
    const float4 gg1 = ((const float4*)g1)[t];
    const float4 bb1 = ((const float4*)b1)[t];
    const float4 sc4 = ((const float4*)sc)[t];
    float4 tv;
    tv.x = ((v.x - mu) * inv * gg1.x + bb1.x) * sc4.x;
    tv.y = ((v.y - mu) * inv * gg1.y + bb1.y) * sc4.y;
    tv.z = ((v.z - mu) * inv * gg1.z + bb1.z) * sc4.z;
    tv.w = ((v.w - mu) * inv * gg1.w + bb1.w) * sc4.w;
    float s2 = tv.x + tv.y + tv.z + tv.w;
    float q2 = tv.x*tv.x + tv.y*tv.y + tv.z*tv.z + tv.w*tv.w;
    float2 r2 = block_reduce2_256(s2, q2);
    float mu2  = r2.x * inv_n;
    float var2 = r2.y * inv_n - mu2 * mu2;
    float inv2 = rsqrtf(var2 + 1e-5f);
    const float4 gg2 = ((const float4*)g2)[t];
    const float4 bb2 = ((const float4*)b2)[t];
    float o0 = (tv.x - mu2) * inv2 * gg2.x + bb2.x;
    float o1 = (tv.y - mu2) * inv2 * gg2.y + bb2.y;
    float o2 = (tv.z - mu2) * inv2 * gg2.z + bb2.z;
    float o3 = (tv.w - mu2) * inv2 * gg2.w + bb2.w;
    uint32_t h0,l0,h1,l1;
    split2(o0, o1, h0, l0);
    split2(o2, o3, h1, l1);
    ((uint2*)(outH + (size_t)row * 512))[t] = make_uint2(h0, h1);
    ((uint2*)(outL + (size_t)row * 512))[t] = make_uint2(l0, l1);
}

// ---------------------------------------------------------------------------
// bf16x3 GEMM, pre-split operands, ldmatrix fragments, cp.async double buffer.
// A: pair-packed [M][ldap]. B: pre-transposed pair-packed [N][ldbt].
// 128x128x32 CTA tile, 256 threads, warp grid 4(M)x2(N), warp tile 32x64.
// ---------------------------------------------------------------------------
__global__ __launch_bounds__(256, 2) void gemm_ps_kernel(
    const uint32_t* __restrict__ Ah, const uint32_t* __restrict__ Al, int ldap,
    const uint32_t* __restrict__ Bh, const uint32_t* __restrict__ Bl, int ldbt,
    const float* __restrict__ bias, const float* __restrict__ cscale,
    float* __restrict__ Cf, uint32_t* __restrict__ Ch, uint32_t* __restrict__ Cl,
    int qscaleCols, int M, int N, int K)
{
    __shared__ uint32_t AhS[2][128][20];
    __shared__ uint32_t AlS[2][128][20];
    __shared__ uint32_t BhS[2][128][20];
    __shared__ uint32_t BlS[2][128][20];

    const int tid  = threadIdx.x;
    const int warp = tid >> 5;
    const int lane = tid & 31;
    const int wm = (warp & 3) * 32;
    const int wn = (warp >> 2) * 64;
    const int q  = lane >> 2;
    const int r  = lane & 3;

    const int rowBase = blockIdx.y * 128;
    const int colBase = blockIdx.x * 128;

    const int nt = K >> 5;                   // k-tiles of 32 (16 pairs)

    // cp.async staging: 2 chunks of 16B per array per thread
    const int srow = tid >> 1;               // 0..127
    const int squad = (tid & 1) * 8;         // 0 or 8

    auto issue = [&](int st, int bb) {
        int kp0 = st * 16;
        #pragma unroll
        for (int it = 0; it < 2; it++) {
            int qd = squad + 4 * it;         // 0,4  or 8,12
            size_t srcA = (size_t)(rowBase + srow) * ldap + kp0 + qd;
            size_t srcB = (size_t)(colBase + srow) * ldbt + kp0 + qd;
            CP16((uint32_t)__cvta_generic_to_shared(&AhS[bb][srow][qd]), Ah + srcA);
            CP16((uint32_t)__cvta_generic_to_shared(&AlS[bb][srow][qd]), Al + srcA);
            CP16((uint32_t)__cvta_generic_to_shared(&BhS[bb][srow][qd]), Bh + srcB);
            CP16((uint32_t)__cvta_generic_to_shared(&BlS[bb][srow][qd]), Bl + srcB);
        }
        CP_COMMIT();
    };

    // ldmatrix per-lane row/col offsets (u32 words, stride 20 per row)
    const int aRowOff = (lane & 7) + 8 * ((lane >> 3) & 1);
    const int aColOff = 4 * (lane >> 4);
    const int bRowOff = (lane & 7) + 8 * (lane >> 4);
    const int bColOff = 4 * ((lane >> 3) & 1);

    float c[2][8][4];
    #pragma unroll
    for (int mf = 0; mf < 2; mf++)
        #pragma unroll
        for (int nf = 0; nf < 8; nf++)
            #pragma unroll
            for (int e = 0; e < 4; e++) c[mf][nf][e] = 0.f;

    issue(0, 0);

    for (int i = 0; i < nt; i++) {
        const int bb = i & 1;
        if (i + 1 < nt) { issue(i + 1, bb ^ 1); CP_WAIT1(); }
        else            { CP_WAIT0(); }
        __syncthreads();

        uint32_t ahBase = (uint32_t)__cvta_generic_to_shared(&AhS[bb][0][0]);
        uint32_t alBase = (uint32_t)__cvta_generic_to_shared(&AlS[bb][0][0]);
        uint32_t bhBase = (uint32_t)__cvta_generic_to_shared(&BhS[bb][0][0]);
        uint32_t blBase = (uint32_t)__cvta_generic_to_shared(&BlS[bb][0][0]);

        #pragma unroll
        for (int ks = 0; ks < 2; ks++) {
            uint32_t ah[2][4], al[2][4];
            #pragma unroll
            for (int mf = 0; mf < 2; mf++) {
                uint32_t off = ((wm + 16 * mf + aRowOff) * 20
                                + 8 * ks + aColOff) * 4;
                ldsm4(ah[mf][0], ah[mf][1], ah[mf][2], ah[mf][3], ahBase + off);
                ldsm4(al[mf][0], al[mf][1], al[mf][2], al[mf][3], alBase + off);
            }
            #pragma unroll
            for (int j = 0; j < 4; j++) {
                uint32_t off = ((wn + 16 * j + bRowOff) * 20
                                + 8 * ks + bColOff) * 4;
                uint32_t bh[4], bl[4];
                ldsm4(bh[0], bh[1], bh[2], bh[3], bhBase + off);
                ldsm4(bl[0], bl[1], bl[2], bl[3], blBase + off);
                #pragma unroll
                for (int sub = 0; sub < 2; sub++) {
                    int nf = 2 * j + sub;
                    #pragma unroll
                    for (int mf = 0; mf < 2; mf++) {
                        mma_bf16(c[mf][nf], ah[mf], bh[2*sub], bh[2*sub+1]);
                        mma_bf16(c[mf][nf], al[mf], bh[2*sub], bh[2*sub+1]);
                        mma_bf16(c[mf][nf], ah[mf], bl[2*sub], bl[2*sub+1]);
                    }
                }
            }
        }
        __syncthreads();
    }

    // ---- epilogue ----
    #pragma unroll
    for (int mf = 0; mf < 2; mf++) {
        int row0 = rowBase + wm + mf * 16 + q;
        #pragma unroll
        for (int half = 0; half < 2; half++) {
            int row = row0 + half * 8;
            #pragma unroll
            for (int nf = 0; nf < 8; nf++) {
                int col = colBase + wn + nf * 8 + r * 2;
                float v0 = c[mf][nf][half * 2 + 0];
                float v1 = c[mf][nf][half * 2 + 1];
                if (bias)   { v0 += bias[col];   v1 += bias[col + 1]; }
                if (col < qscaleCols) { v0 *= 0.125f; v1 *= 0.125f; }
                if (Cf) {
                    if (cscale) { v0 *= cscale[col]; v1 *= cscale[col + 1]; }
                    *(float2*)(Cf + (size_t)row * N + col) = make_float2(v0, v1);
                } else {
                    uint32_t hh, ll;
                    split2(v0, v1, hh, ll);
                    size_t off = (size_t)row * (N >> 1) + (col >> 1);
                    Ch[off] = hh;
                    Cl[off] = ll;
                }
            }
        }
    }
}

// ---------------------------------------------------------------------------
// bf16x3 tensor-core flash attention (pre-split inputs) — from R8 (passed).
// ---------------------------------------------------------------------------
__global__ __launch_bounds__(256) void attn_tc_kernel(
    const uint32_t* __restrict__ qkvh, const uint32_t* __restrict__ qkvl,
    uint32_t* __restrict__ outH, uint32_t* __restrict__ outL)
{
    __shared__ uint32_t KpH[64][36];
    __shared__ uint32_t KpL[64][36];
    __shared__ uint32_t VpH[32][72];
    __shared__ uint32_t VpL[32][72];

    const int bh = blockIdx.y;
    const int b  = bh >> 4;
    const int h  = bh & 15;
    const int tid  = threadIdx.x;
    const int warp = tid >> 5;
    const int lane = tid & 31;
    const int q = lane >> 2;
    const int r = lane & 3;

    const int qrow = blockIdx.x * 128 + warp * 16;

    uint32_t qh[4][4], ql[4][4];
    {
        const uint32_t* Q0h = qkvh + (size_t)(b * SEQ + qrow + q) * 1536 + 32 * h;
        const uint32_t* Q1h = Q0h + 8 * 1536;
        const uint32_t* Q0l = qkvl + (size_t)(b * SEQ + qrow + q) * 1536 + 32 * h;
        const uint32_t* Q1l = Q0l + 8 * 1536;
        #pragma unroll
        for (int ks = 0; ks < 4; ks++) {
            int p = 8 * ks + r;
            qh[ks][0] = Q0h[p];     qh[ks][1] = Q1h[p];
            qh[ks][2] = Q0h[p + 4]; qh[ks][3] = Q1h[p + 4];
            ql[ks][0] = Q0l[p];     ql[ks][1] = Q1l[p];
            ql[ks][2] = Q0l[p + 4]; ql[ks][3] = Q1l[p + 4];
        }
    }

    float o[8][4];
    #pragma unroll
    for (int nf = 0; nf < 8; nf++)
        #pragma unroll
        for (int e = 0; e < 4; e++) o[nf][e] = 0.f;
    float m0 = -1e30f, m1 = -1e30f;
    float l0 = 0.f, l1 = 0.f;

    const size_t baseK = (size_t)(b * SEQ) * 1536 + 512 + 32 * h;
    const size_t baseV = (size_t)(b * SEQ) * 1536 + 1024 + 32 * h;

    for (int j0 = 0; j0 < SEQ; j0 += 64) {
        __syncthreads();
        #pragma unroll
        for (int it = 0; it < 2; it++) {
            int idx = tid + it * 256;
            int key = idx >> 3;
            int c   = (idx & 7) * 4;
            size_t src = baseK + (size_t)(j0 + key) * 1536 + c;
            *(uint4*)&KpH[key][c] = *(const uint4*)(qkvh + src);
            *(uint4*)&KpL[key][c] = *(const uint4*)(qkvl + src);
        }
        #pragma unroll
        for (int it = 0; it < 2; it++) {
            int idx = tid + it * 256;
            int kp  = idx >> 4;
            int dpp = (idx & 15) * 2;
            size_t src = baseV + (size_t)(j0 + 2 * kp) * 1536 + dpp;
            uint2 aH = *(const uint2*)(qkvh + src);
            uint2 bH = *(const uint2*)(qkvh + src + 1536);
            uint2 aL = *(const uint2*)(qkvl + src);
            uint2 bL = *(const uint2*)(qkvl + src + 1536);
            VpH[kp][2*dpp    ] = __byte_perm(aH.x, bH.x, 0x5410);
            VpH[kp][2*dpp + 1] = __byte_perm(aH.x, bH.x, 0x7632);
            VpH[kp][2*dpp + 2] = __byte_perm(aH.y, bH.y, 0x5410);
            VpH[kp][2*dpp + 3] = __byte_perm(aH.y, bH.y, 0x7632);
            VpL[kp][2*dpp    ] = __byte_perm(aL.x, bL.x, 0x5410);
            VpL[kp][2*dpp + 1] = __byte_perm(aL.x, bL.x, 0x7632);
            VpL[kp][2*dpp + 2] = __byte_perm(aL.y, bL.y, 0x5410);
            VpL[kp][2*dpp + 3] = __byte_perm(aL.y, bL.y, 0x7632);
        }
        __syncthreads();

        float s[8][4];
        #pragma unroll
        for (int nf = 0; nf < 8; nf++)
            #pragma unroll
            for (int e = 0; e < 4; e++) s[nf][e] = 0.f;

        #pragma unroll
        for (int ks = 0; ks < 4; ks++) {
            #pragma unroll
            for (int nf = 0; nf < 8; nf++) {
                int key = 8 * nf + q;
                uint32_t bh0 = KpH[key][8 * ks + r];
                uint32_t bh1 = KpH[key][8 * ks + r + 4];
                uint32_t bl0 = KpL[key][8 * ks + r];
                uint32_t bl1 = KpL[key][8 * ks + r + 4];
                mma_bf16(s[nf], qh[ks], bh0, bh1);
                mma_bf16(s[nf], ql[ks], bh0, bh1);
                mma_bf16(s[nf], qh[ks], bl0, bl1);
            }
        }

        float t0 = -1e30f, t1 = -1e30f;
        #pragma unroll
        for (int nf = 0; nf < 8; nf++) {
            t0 = fmaxf(t0, fmaxf(s[nf][0], s[nf][1]));
            t1 = fmaxf(t1, fmaxf(s[nf][2], s[nf][3]));
        }
        t0 = fmaxf(t0, __shfl_xor_sync(0xffffffffu, t0, 1));
        t0 = fmaxf(t0, __shfl_xor_sync(0xffffffffu, t0, 2));
        t1 = fmaxf(t1, __shfl_xor_sync(0xffffffffu, t1, 1));
        t1 = fmaxf(t1, __shfl_xor_sync(0xffffffffu, t1, 2));

        float mn0 = fmaxf(m0, t0), mn1 = fmaxf(m1, t1);
        float a0 = __expf(m0 - mn0), a1 = __expf(m1 - mn1);
        m0 = mn0; m1 = mn1;
        l0 *= a0; l1 *= a1;
        #pragma unroll
        for (int nf = 0; nf < 8; nf++) {
            o[nf][0] *= a0; o[nf][1] *= a0;
            o[nf][2] *= a1; o[nf][3] *= a1;
        }

        uint32_t pah[4][4], pal[4][4];
        float sum0 = 0.f, sum1 = 0.f;
        #pragma unroll
        for (int nf = 0; nf < 8; nf++) {
            float p0 = __expf(s[nf][0] - m0);
            float p1 = __expf(s[nf][1] - m0);
            float p2 = __expf(s[nf][2] - m1);
            float p3 = __expf(s[nf][3] - m1);
            sum0 += p0 + p1; sum1 += p2 + p3;
            int ks = nf >> 1, part = nf & 1;
            split2(p0, p1, pah[ks][2 * part],     pal[ks][2 * part]);
            split2(p2, p3, pah[ks][2 * part + 1], pal[ks][2 * part + 1]);
        }
        sum0 += __shfl_xor_sync(0xffffffffu, sum0, 1);
        sum0 += __shfl_xor_sync(0xffffffffu, sum0, 2);
        sum1 += __shfl_xor_sync(0xffffffffu, sum1, 1);
        sum1 += __shfl_xor_sync(0xffffffffu, sum1, 2);
        l0 += sum0; l1 += sum1;

        #pragma unroll
        for (int ks = 0; ks < 4; ks++) {
            #pragma unroll
            for (int nf = 0; nf < 8; nf++) {
                int d = 8 * nf + q;
                uint32_t bh0 = VpH[8 * ks + r    ][d];
                uint32_t bh1 = VpH[8 * ks + r + 4][d];
                uint32_t bl0 = VpL[8 * ks + r    ][d];
                uint32_t bl1 = VpL[8 * ks + r + 4][d];
                mma_bf16(o[nf], pah[ks], bh0, bh1);
                mma_bf16(o[nf], pal[ks], bh0, bh1);
                mma_bf16(o[nf], pah[ks], bl0, bl1);
            }
        }
    }

    float inv0 = 1.0f / l0, inv1 = 1.0f / l1;
    uint32_t* O0h = outH + (size_t)(b * SEQ + qrow + q) * 512 + 32 * h;
    uint32_t* O0l = outL + (size_t)(b * SEQ + qrow + q) * 512 + 32 * h;
    uint32_t* O1h = O0h + 8 * 512;
    uint32_t* O1l = O0l + 8 * 512;
    #pragma unroll
    for (int nf = 0; nf < 8; nf++) {
        int pc = 4 * nf + r;
        uint32_t hh, ll;
        split2(o[nf][0] * inv0, o[nf][1] * inv0, hh, ll);
        O0h[pc] = hh; O0l[pc] = ll;
        split2(o[nf][2] * inv1, o[nf][3] * inv1, hh, ll);
        O1h[pc] = hh; O1l[pc] = ll;
    }
}

// ---------------------------------------------------------------------------
__global__ __launch_bounds__(256) void geglu_kernel(
    const float* __restrict__ u,
    uint32_t* __restrict__ outH, uint32_t* __restrict__ outL)
{
    int i = blockIdx.x * 256 + threadIdx.x;
    int row = i >> 10;
    int c4  = i & 1023;
    const float4* base = (const float4*)(u + (size_t)row * (2 * FFDIM));
    float4 a = base[c4];
    float4 g = base[c4 + 1024];
    float o0 = a.x * g.x * normcdff(g.x);
    float o1 = a.y * g.y * normcdff(g.y);
    float o2 = a.z * g.z * normcdff(g.z);
    float o3 = a.w * g.w * normcdff(g.w);
    uint32_t h0,l0,h1,l1;
    split2(o0, o1, h0, l0);
    split2(o2, o3, h1, l1);
    ((uint2*)(outH + (size_t)row * 2048))[c4] = make_uint2(h0, h1);
    ((uint2*)(outL + (size_t)row * 2048))[c4] = make_uint2(l0, l1);
}

// ---------------------------------------------------------------------------
extern "C" void kernel_launch(void* const* d_in, const int* in_sizes, int n_in,
                              void* d_out, int out_size)
{
    const float* x            = (const float*)d_in[0];
    const float* w_qkv        = (const float*)d_in[2];
    const float* w_out        = (const float*)d_in[3];
    const float* b_out        = (const float*)d_in[4];
    const float* ln_inner_g   = (const float*)d_in[5];
    const float* ln_inner_b   = (const float*)d_in[6];
    const float* ln_pre_attn_g= (const float*)d_in[7];
    const float* ln_pre_attn_b= (const float*)d_in[8];
    const float* scale_attn   = (const float*)d_in[9];
    const float* w1           = (const float*)d_in[10];
    const float* b1           = (const float*)d_in[11];
    const float* w2           = (const float*)d_in[12];
    const float* b2           = (const float*)d_in[13];
    const float* ln_pre_ff_g  = (const float*)d_in[14];
    const float* ln_pre_ff_b  = (const float*)d_in[15];
    const float* scale_ff     = (const float*)d_in[16];
    float* out = (float*)d_out;

    uint32_t *whP, *wlP, *ahP, *alP, *qhP, *qlP;
    float *uP, *pP;
    cudaGetSymbolAddress((void**)&whP, g_wh);
    cudaGetSymbolAddress((void**)&wlP, g_wl);
    cudaGetSymbolAddress((void**)&ahP, g_ah);
    cudaGetSymbolAddress((void**)&alP, g_al);
    cudaGetSymbolAddress((void**)&qhP, g_qh);
    cudaGetSymbolAddress((void**)&qlP, g_ql);
    cudaGetSymbolAddress((void**)&uP,  g_u);
    cudaGetSymbolAddress((void**)&pP,  g_p);

    // 0) split + transpose weights -> Wt[n][K/2] pair-packed hi/lo
    split_wt_kernel<<<dim3(3072/64, 1024/32), 256>>>(w_qkv, whP + OFF_WQKV, wlP + OFF_WQKV, 3072, 512);
    split_wt_kernel<<<dim3(1024/64, 1024/32), 256>>>(w_out, whP + OFF_WOUT, wlP + OFF_WOUT, 1024, 512);
    split_wt_kernel<<<dim3(8192/64, 1024/32), 256>>>(w1,    whP + OFF_W1,   wlP + OFF_W1,   8192, 512);
    split_wt_kernel<<<dim3(1024/64, 4096/32), 256>>>(w2,    whP + OFF_W2,   wlP + OFF_W2,   1024, 2048);

    // 1) h = LN_pre_attn(x) -> packed
    ln_kernel<<<NTOK, 256>>>(x, ln_pre_attn_g, ln_pre_attn_b, ahP, alP);

    // 2) qkv = h @ w_qkv -> packed (Q cols pre-scaled by 0.125)
    gemm_ps_kernel<<<dim3(3072/128, NTOK/128), 256>>>(
        ahP, alP, 512, whP + OFF_WQKV, wlP + OFF_WQKV, 512,
        nullptr, nullptr, nullptr, qhP, qlP, 1024, NTOK, 3072, DMODEL);

    // 3) attention -> packed g_ah/g_al
    attn_tc_kernel<<<dim3(SEQ/128, 2 * NHEAD), 256>>>(qhP, qlP, ahP, alP);

    // 4) proj = attn @ w_out + b_out -> fp32 g_p
    gemm_ps_kernel<<<dim3(DMODEL/128, NTOK/128), 256>>>(
        ahP, alP, 512, whP + OFF_WOUT, wlP + OFF_WOUT, 512,
        b_out, nullptr, pP, nullptr, nullptr, 0, NTOK, DMODEL, DMODEL);

    // 5) h2 = LN_pre_ff(LN_inner(p) * scale_attn) -> packed
    dln_kernel<<<NTOK, 256>>>(pP, ln_inner_g, ln_inner_b, scale_attn,
                              ln_pre_ff_g, ln_pre_ff_b, ahP, alP);

    // 6) u = h2 @ w1 + b1 -> fp32 g_u
    gemm_ps_kernel<<<dim3(2*FFDIM/128, NTOK/128), 256>>>(
        ahP, alP, 512, whP + OFF_W1, wlP + OFF_W1, 512,
        b1, nullptr, uP, nullptr, nullptr, 0, NTOK, 2 * FFDIM, DMODEL);

    // 7) GeGLU -> packed (row stride 2048 pairs)
    geglu_kernel<<<(NTOK * (FFDIM/4)) / 256, 256>>>(uP, ahP, alP);

    // 8) out = geglu @ w2 + b2, * scale_ff -> d_out
    gemm_ps_kernel<<<dim3(DMODEL/128, NTOK/128), 256>>>(
        ahP, alP, 2048, whP + OFF_W2, wlP + OFF_W2, 2048,
        b2, scale_ff, out, nullptr, nullptr, 0, NTOK, DMODEL, FFDIM);
}

// round 14
// speedup vs baseline: 1.0427x; 1.0427x over previous
#include <cuda_runtime.h>
#include <cuda_bf16.h>
#include <math.h>
#include <stdint.h>

// ----------------------------------------------------------------------------
// TransformerLayer: B=2, L=2048, D=1024, H=16, HD=64, FF=4096
// bf16x3 split precision, HMMA (mma.sync) only — tcgen05 is not available
// through this harness's compute_103 PTX stage.
// GEMM: CTA 256x128, warp tile 64x64, scalar-LDS fragments (conflict-free
// stride-20 rows), 3-stage cp.async ring, one __syncthreads per k-tile.
// ----------------------------------------------------------------------------

#define NTOK   4096
#define DMODEL 1024
#define NHEAD  16
#define HDIM   64
#define FFDIM  4096
#define SEQ    2048

// Weight split offsets (u32 pair units). Layout: Wt[n][K/2] (n-major).
#define OFF_WQKV 0
#define OFF_WOUT (512 * 3072)
#define OFF_W1   (OFF_WOUT + 512 * 1024)
#define OFF_W2   (OFF_W1 + 512 * 8192)
#define WTOT     (OFF_W2 + 2048 * 1024)

__device__ uint32_t g_wh[WTOT];
__device__ uint32_t g_wl[WTOT];
__device__ uint32_t g_ah[(size_t)NTOK * 2048];
__device__ uint32_t g_al[(size_t)NTOK * 2048];
__device__ uint32_t g_qh[(size_t)NTOK * 1536];
__device__ uint32_t g_ql[(size_t)NTOK * 1536];
__device__ float    g_u [(size_t)NTOK * 2 * FFDIM];
__device__ float    g_p [(size_t)NTOK * DMODEL];

// ---------------------------------------------------------------------------
__device__ __forceinline__ void split2(float x, float y,
                                       uint32_t& hi, uint32_t& lo) {
    __nv_bfloat162 h = __floats2bfloat162_rn(x, y);
    float lx = x - __bfloat162float(h.x);
    float ly = y - __bfloat162float(h.y);
    __nv_bfloat162 l = __floats2bfloat162_rn(lx, ly);
    hi = *(uint32_t*)&h;
    lo = *(uint32_t*)&l;
}

__device__ __forceinline__ void mma_bf16(float c[4], const uint32_t a[4],
                                         uint32_t b0, uint32_t b1) {
    asm volatile(
        "mma.sync.aligned.m16n8k16.row.col.f32.bf16.bf16.f32 "
        "{%0,%1,%2,%3}, {%4,%5,%6,%7}, {%8,%9}, {%0,%1,%2,%3};"
        : "+f"(c[0]), "+f"(c[1]), "+f"(c[2]), "+f"(c[3])
        : "r"(a[0]), "r"(a[1]), "r"(a[2]), "r"(a[3]), "r"(b0), "r"(b1));
}

#define CP16(smem_u32_addr, gptr) \
    asm volatile("cp.async.cg.shared.global [%0], [%1], 16;" \
                 :: "r"(smem_u32_addr), "l"(gptr))
#define CP_COMMIT() asm volatile("cp.async.commit_group;")
#define CP_WAIT1()  asm volatile("cp.async.wait_group 1;")
#define CP_WAIT0()  asm volatile("cp.async.wait_group 0;")

__device__ __forceinline__ uint32_t smem_u32(const void* p) {
    return (uint32_t)__cvta_generic_to_shared(p);
}

// ---------------------------------------------------------------------------
// Weight split + transpose: W[K,N] fp32 -> Wt hi/lo [N][K/2] u32 pair-packed.
// ---------------------------------------------------------------------------
__global__ __launch_bounds__(256) void split_wt_kernel(
    const float* __restrict__ W, uint32_t* __restrict__ Wh,
    uint32_t* __restrict__ Wl, int N, int Khalf)
{
    __shared__ uint32_t Sh[64][20];
    __shared__ uint32_t Sl[64][20];
    const int n0  = blockIdx.x * 64;
    const int kp0 = blockIdx.y * 16;
    const int t = threadIdx.x;
    {
        int kp = t >> 4;
        int n4 = (t & 15) * 4;
        const float* W0 = W + (size_t)(2 * (kp0 + kp)) * N + n0 + n4;
        float4 r0 = *(const float4*)(W0);
        float4 r1 = *(const float4*)(W0 + N);
        uint32_t h, l;
        split2(r0.x, r1.x, h, l); Sh[n4+0][kp] = h; Sl[n4+0][kp] = l;
        split2(r0.y, r1.y, h, l); Sh[n4+1][kp] = h; Sl[n4+1][kp] = l;
        split2(r0.z, r1.z, h, l); Sh[n4+2][kp] = h; Sl[n4+2][kp] = l;
        split2(r0.w, r1.w, h, l); Sh[n4+3][kp] = h; Sl[n4+3][kp] = l;
    }
    __syncthreads();
    {
        int n  = t >> 2;
        int kq = (t & 3) * 4;
        size_t off = (size_t)(n0 + n) * Khalf + kp0 + kq;
        *(uint4*)(Wh + off) = *(uint4*)&Sh[n][kq];
        *(uint4*)(Wl + off) = *(uint4*)&Sl[n][kq];
    }
}

// ---------------------------------------------------------------------------
__device__ __forceinline__ float2 block_reduce2_256(float a, float b) {
    #pragma unroll
    for (int o = 16; o > 0; o >>= 1) {
        a += __shfl_xor_sync(0xffffffffu, a, o);
        b += __shfl_xor_sync(0xffffffffu, b, o);
    }
    __shared__ float sa[8], sb[8];
    int w = threadIdx.x >> 5, lane = threadIdx.x & 31;
    __syncthreads();
    if (lane == 0) { sa[w] = a; sb[w] = b; }
    __syncthreads();
    float ta = 0.f, tb = 0.f;
    #pragma unroll
    for (int i = 0; i < 8; i++) { ta += sa[i]; tb += sb[i]; }
    return make_float2(ta, tb);
}

__global__ __launch_bounds__(256) void ln_kernel(
    const float* __restrict__ in, const float* __restrict__ g,
    const float* __restrict__ b,
    uint32_t* __restrict__ outH, uint32_t* __restrict__ outL)
{
    int row = blockIdx.x;
    int t = threadIdx.x;
    const float4 v = ((const float4*)(in + (size_t)row * DMODEL))[t];
    float s = v.x + v.y + v.z + v.w;
    float q = v.x*v.x + v.y*v.y + v.z*v.z + v.w*v.w;
    float2 r = block_reduce2_256(s, q);
    const float inv_n = 1.0f / DMODEL;
    float mu  = r.x * inv_n;
    float var = r.y * inv_n - mu * mu;
    float inv = rsqrtf(var + 1e-5f);
    const float4 gg = ((const float4*)g)[t];
    const float4 bb = ((const float4*)b)[t];
    float o0 = (v.x - mu) * inv * gg.x + bb.x;
    float o1 = (v.y - mu) * inv * gg.y + bb.y;
    float o2 = (v.z - mu) * inv * gg.z + bb.z;
    float o3 = (v.w - mu) * inv * gg.w + bb.w;
    uint32_t h0,l0,h1,l1;
    split2(o0, o1, h0, l0);
    split2(o2, o3, h1, l1);
    ((uint2*)(outH + (size_t)row * 512))[t] = make_uint2(h0, h1);
    ((uint2*)(outL + (size_t)row * 512))[t] = make_uint2(l0, l1);
}

__global__ __launch_bounds__(256) void dln_kernel(
    const float* __restrict__ in,
    const float* __restrict__ g1, const float* __restrict__ b1,
    const float* __restrict__ sc,
    const float* __restrict__ g2, const float* __restrict__ b2,
    uint32_t* __restrict__ outH, uint32_t* __restrict__ outL)
{
    int row = blockIdx.x;
    int t = threadIdx.x;
    const float inv_n = 1.0f / DMODEL;
    const float4 v = ((const float4*)(in + (size_t)row * DMODEL))[t];
    float s = v.x + v.y + v.z + v.w;
    float q = v.x*v.x + v.y*v.y + v.z*v.z + v.w*v.w;
    float2 r = block_reduce2_256(s, q);
    float mu  = r.x * inv_n;
    float var = r.y * inv_n - mu * mu;
    float inv = rsqrtf(var + 1e-5f);
    const float4 gg1 = ((const float4*)g1)[t];
    const float4 bb1 = ((const float4*)b1)[t];
    const float4 sc4 = ((const float4*)sc)[t];
    float4 tv;
    tv.x = ((v.x - mu) * inv * gg1.x + bb1.x) * sc4.x;
    tv.y = ((v.y - mu) * inv * gg1.y + bb1.y) * sc4.y;
    tv.z = ((v.z - mu) * inv * gg1.z + bb1.z) * sc4.z;
    tv.w = ((v.w - mu) * inv * gg1.w + bb1.w) * sc4.w;
    float s2 = tv.x + tv.y + tv.z + tv.w;
    float q2 = tv.x*tv.x + tv.y*tv.y + tv.z*tv.z + tv.w*tv.w;
    float2 r2 = block_reduce2_256(s2, q2);
    float mu2  = r2.x * inv_n;
    float var2 = r2.y * inv_n - mu2 * mu2;
    float inv2 = rsqrtf(var2 + 1e-5f);
    const float4 gg2 = ((const float4*)g2)[t];
    const float4 bb2 = ((const float4*)b2)[t];
    float o0 = (tv.x - mu2) * inv2 * gg2.x + bb2.x;
    float o1 = (tv.y - mu2) * inv2 * gg2.y + bb2.y;
    float o2 = (tv.z - mu2) * inv2 * gg2.z + bb2.z;
    float o3 = (tv.w - mu2) * inv2 * gg2.w + bb2.w;
    uint32_t h0,l0,h1,l1;
    split2(o0, o1, h0, l0);
    split2(o2, o3, h1, l1);
    ((uint2*)(outH + (size_t)row * 512))[t] = make_uint2(h0, h1);
    ((uint2*)(outL + (size_t)row * 512))[t] = make_uint2(l0, l1);
}

// ---------------------------------------------------------------------------
// bf16x3 GEMM: C[M,N] = A[M,K] @ Wt[N,K]^T (+bias)(*cscale / *0.125 Q-cols)
// A: pair-packed [M][ldap]. B: n-major pair-packed [N][ldbt].
// CTA 256x128, 256 threads, warp grid 4(M)x2(N), warp tile 64x64.
// 3-stage cp.async ring, stride-20 smem rows, one __syncthreads per k-tile.
// Dynamic smem (u32): AhS[3][256][20] AlS[...] BhS[3][128][20] BlS[...]
// ---------------------------------------------------------------------------
#define ASTRIDE 20
#define A_BUF   (256 * ASTRIDE)          // 5120 u32 per stage
#define B_BUF   (128 * ASTRIDE)          // 2560 u32 per stage
#define OFF_ALS (3 * A_BUF)              // 15360
#define OFF_BHS (2 * 3 * A_BUF)          // 30720
#define OFF_BLS (OFF_BHS + 3 * B_BUF)    // 38400
#define GSMEM_U32 (OFF_BLS + 3 * B_BUF)  // 46080 u32 = 184320 B
#define GSMEM_B  (GSMEM_U32 * 4)

__global__ __launch_bounds__(256, 1) void gemm_ps_kernel(
    const uint32_t* __restrict__ Ah, const uint32_t* __restrict__ Al, int ldap,
    const uint32_t* __restrict__ Bh, const uint32_t* __restrict__ Bl, int ldbt,
    const float* __restrict__ bias, const float* __restrict__ cscale,
    float* __restrict__ Cf, uint32_t* __restrict__ Ch, uint32_t* __restrict__ Cl,
    int qscaleCols, int M, int N, int K)
{
    extern __shared__ uint32_t sm[];
    uint32_t* AhS = sm;
    uint32_t* AlS = sm + OFF_ALS;
    uint32_t* BhS = sm + OFF_BHS;
    uint32_t* BlS = sm + OFF_BLS;

    const int tid  = threadIdx.x;
    const int warp = tid >> 5;
    const int lane = tid & 31;
    const int wm = (warp & 3) * 64;      // warp M base (64-row tile)
    const int wn = (warp >> 2) * 64;     // warp N base (64-col tile)
    const int q  = lane >> 2;
    const int r  = lane & 3;

    const int rowBase = blockIdx.y * 256;
    const int colBase = blockIdx.x * 128;
    const int nt = K >> 5;               // k-tiles of 32 (16 pairs)

    auto stage = [&](int j, int bb) {
        const int kp0 = j * 16;
        #pragma unroll
        for (int it = 0; it < 4; it++) {
            int id = tid + 256 * it;     // 0..1023
            int row = id >> 2;
            int quad = (id & 3) * 4;
            size_t src = (size_t)(rowBase + row) * ldap + kp0 + quad;
            int d = (bb * 256 + row) * ASTRIDE + quad;
            CP16(smem_u32(&AhS[d]), Ah + src);
            CP16(smem_u32(&AlS[d]), Al + src);
        }
        #pragma unroll
        for (int it = 0; it < 2; it++) {
            int id = tid + 256 * it;     // 0..511
            int row = id >> 2;
            int quad = (id & 3) * 4;
            size_t src = (size_t)(colBase + row) * ldbt + kp0 + quad;
            int d = (bb * 128 + row) * ASTRIDE + quad;
            CP16(smem_u32(&BhS[d]), Bh + src);
            CP16(smem_u32(&BlS[d]), Bl + src);
        }
        CP_COMMIT();
    };

    float c[4][8][4];
    #pragma unroll
    for (int mf = 0; mf < 4; mf++)
        #pragma unroll
        for (int nf = 0; nf < 8; nf++)
            #pragma unroll
            for (int e = 0; e < 4; e++) c[mf][nf][e] = 0.f;

    stage(0, 0);
    if (nt > 1) stage(1, 1);

    for (int i = 0; i < nt; i++) {
        const int bb = i % 3;
        if (i + 1 < nt) { CP_WAIT1(); } else { CP_WAIT0(); }
        __syncthreads();
        if (i + 2 < nt) stage(i + 2, (i + 2) % 3);

        const uint32_t* Abh = AhS + bb * A_BUF;
        const uint32_t* Abl = AlS + bb * A_BUF;
        const uint32_t* Bbh = BhS + bb * B_BUF;
        const uint32_t* Bbl = BlS + bb * B_BUF;

        #pragma unroll
        for (int ks = 0; ks < 2; ks++) {
            const int kk = ks * 8;
            uint32_t ah[4][4], al[4][4];
            #pragma unroll
            for (int mf = 0; mf < 4; mf++) {
                int m0 = wm + mf * 16 + q;
                ah[mf][0] = Abh[m0 * ASTRIDE + kk + r];
                ah[mf][1] = Abh[(m0 + 8) * ASTRIDE + kk + r];
                ah[mf][2] = Abh[m0 * ASTRIDE + kk + r + 4];
                ah[mf][3] = Abh[(m0 + 8) * ASTRIDE + kk + r + 4];
                al[mf][0] = Abl[m0 * ASTRIDE + kk + r];
                al[mf][1] = Abl[(m0 + 8) * ASTRIDE + kk + r];
                al[mf][2] = Abl[m0 * ASTRIDE + kk + r + 4];
                al[mf][3] = Abl[(m0 + 8) * ASTRIDE + kk + r + 4];
            }
            #pragma unroll
            for (int nf = 0; nf < 8; nf++) {
                int n = wn + nf * 8 + q;
                uint32_t bh0 = Bbh[n * ASTRIDE + kk + r];
                uint32_t bh1 = Bbh[n * ASTRIDE + kk + r + 4];
                uint32_t bl0 = Bbl[n * ASTRIDE + kk + r];
                uint32_t bl1 = Bbl[n * ASTRIDE + kk + r + 4];
                #pragma unroll
                for (int mf = 0; mf < 4; mf++) {
                    mma_bf16(c[mf][nf], ah[mf], bh0, bh1);
                    mma_bf16(c[mf][nf], al[mf], bh0, bh1);
                    mma_bf16(c[mf][nf], ah[mf], bl0, bl1);
                }
            }
        }
        // no trailing sync: stage(i+2) wrote buffer (i+2)%3, untouched by
        // compute(i); compute(i+1) syncs before reading its buffer.
    }

    // ---- epilogue ----
    #pragma unroll
    for (int mf = 0; mf < 4; mf++) {
        int row0 = rowBase + wm + mf * 16 + q;
        #pragma unroll
        for (int half = 0; half < 2; half++) {
            int row = row0 + half * 8;
            #pragma unroll
            for (int nf = 0; nf < 8; nf++) {
                int col = colBase + wn + nf * 8 + r * 2;
                float v0 = c[mf][nf][half * 2 + 0];
                float v1 = c[mf][nf][half * 2 + 1];
                if (bias)   { v0 += bias[col];   v1 += bias[col + 1]; }
                if (col < qscaleCols) { v0 *= 0.125f; v1 *= 0.125f; }
                if (Cf) {
                    if (cscale) { v0 *= cscale[col]; v1 *= cscale[col + 1]; }
                    *(float2*)(Cf + (size_t)row * N + col) = make_float2(v0, v1);
                } else {
                    uint32_t hh, ll;
                    split2(v0, v1, hh, ll);
                    size_t off = (size_t)row * (N >> 1) + (col >> 1);
                    Ch[off] = hh;
                    Cl[off] = ll;
                }
            }
        }
    }
}

// ---------------------------------------------------------------------------
// bf16x3 HMMA flash attention (validated R8).
// ---------------------------------------------------------------------------
__global__ __launch_bounds__(256) void attn_tc_kernel(
    const uint32_t* __restrict__ qkvh, const uint32_t* __restrict__ qkvl,
    uint32_t* __restrict__ outH, uint32_t* __restrict__ outL)
{
    __shared__ uint32_t KpH[64][36];
    __shared__ uint32_t KpL[64][36];
    __shared__ uint32_t VpH[32][72];
    __shared__ uint32_t VpL[32][72];

    const int bh = blockIdx.y;
    const int b  = bh >> 4;
    const int h  = bh & 15;
    const int tid  = threadIdx.x;
    const int warp = tid >> 5;
    const int lane = tid & 31;
    const int q = lane >> 2;
    const int r = lane & 3;

    const int qrow = blockIdx.x * 128 + warp * 16;

    uint32_t qh[4][4], ql[4][4];
    {
        const uint32_t* Q0h = qkvh + (size_t)(b * SEQ + qrow + q) * 1536 + 32 * h;
        const uint32_t* Q1h = Q0h + 8 * 1536;
        const uint32_t* Q0l = qkvl + (size_t)(b * SEQ + qrow + q) * 1536 + 32 * h;
        const uint32_t* Q1l = Q0l + 8 * 1536;
        #pragma unroll
        for (int ks = 0; ks < 4; ks++) {
            int p = 8 * ks + r;
            qh[ks][0] = Q0h[p];     qh[ks][1] = Q1h[p];
            qh[ks][2] = Q0h[p + 4]; qh[ks][3] = Q1h[p + 4];
            ql[ks][0] = Q0l[p];     ql[ks][1] = Q1l[p];
            ql[ks][2] = Q0l[p + 4]; ql[ks][3] = Q1l[p + 4];
        }
    }

    float o[8][4];
    #pragma unroll
    for (int nf = 0; nf < 8; nf++)
        #pragma unroll
        for (int e = 0; e < 4; e++) o[nf][e] = 0.f;
    float m0 = -1e30f, m1 = -1e30f;
    float l0 = 0.f, l1 = 0.f;

    const size_t baseK = (size_t)(b * SEQ) * 1536 + 512 + 32 * h;
    const size_t baseV = (size_t)(b * SEQ) * 1536 + 1024 + 32 * h;

    for (int j0 = 0; j0 < SEQ; j0 += 64) {
        __syncthreads();
        #pragma unroll
        for (int it = 0; it < 2; it++) {
            int idx = tid + it * 256;
            int key = idx >> 3;
            int c   = (idx & 7) * 4;
            size_t src = baseK + (size_t)(j0 + key) * 1536 + c;
            *(uint4*)&KpH[key][c] = *(const uint4*)(qkvh + src);
            *(uint4*)&KpL[key][c] = *(const uint4*)(qkvl + src);
        }
        #pragma unroll
        for (int it = 0; it < 2; it++) {
            int idx = tid + it * 256;
            int kp  = idx >> 4;
            int dpp = (idx & 15) * 2;
            size_t src = baseV + (size_t)(j0 + 2 * kp) * 1536 + dpp;
            uint2 aH = *(const uint2*)(qkvh + src);
            uint2 bH = *(const uint2*)(qkvh + src + 1536);
            uint2 aL = *(const uint2*)(qkvl + src);
            uint2 bL = *(const uint2*)(qkvl + src + 1536);
            VpH[kp][2*dpp    ] = __byte_perm(aH.x, bH.x, 0x5410);
            VpH[kp][2*dpp + 1] = __byte_perm(aH.x, bH.x, 0x7632);
            VpH[kp][2*dpp + 2] = __byte_perm(aH.y, bH.y, 0x5410);
            VpH[kp][2*dpp + 3] = __byte_perm(aH.y, bH.y, 0x7632);
            VpL[kp][2*dpp    ] = __byte_perm(aL.x, bL.x, 0x5410);
            VpL[kp][2*dpp + 1] = __byte_perm(aL.x, bL.x, 0x7632);
            VpL[kp][2*dpp + 2] = __byte_perm(aL.y, bL.y, 0x5410);
            VpL[kp][2*dpp + 3] = __byte_perm(aL.y, bL.y, 0x7632);
        }
        __syncthreads();

        float s[8][4];
        #pragma unroll
        for (int nf = 0; nf < 8; nf++)
            #pragma unroll
            for (int e = 0; e < 4; e++) s[nf][e] = 0.f;

        #pragma unroll
        for (int ks = 0; ks < 4; ks++) {
            #pragma unroll
            for (int nf = 0; nf < 8; nf++) {
                int key = 8 * nf + q;
                uint32_t bh0 = KpH[key][8 * ks + r];
                uint32_t bh1 = KpH[key][8 * ks + r + 4];
                uint32_t bl0 = KpL[key][8 * ks + r];
                uint32_t bl1 = KpL[key][8 * ks + r + 4];
                mma_bf16(s[nf], qh[ks], bh0, bh1);
                mma_bf16(s[nf], ql[ks], bh0, bh1);
                mma_bf16(s[nf], qh[ks], bl0, bl1);
            }
        }

        float t0 = -1e30f, t1 = -1e30f;
        #pragma unroll
        for (int nf = 0; nf < 8; nf++) {
            t0 = fmaxf(t0, fmaxf(s[nf][0], s[nf][1]));
            t1 = fmaxf(t1, fmaxf(s[nf][2], s[nf][3]));
        }
        t0 = fmaxf(t0, __shfl_xor_sync(0xffffffffu, t0, 1));
        t0 = fmaxf(t0, __shfl_xor_sync(0xffffffffu, t0, 2));
        t1 = fmaxf(t1, __shfl_xor_sync(0xffffffffu, t1, 1));
        t1 = fmaxf(t1, __shfl_xor_sync(0xffffffffu, t1, 2));

        float mn0 = fmaxf(m0, t0), mn1 = fmaxf(m1, t1);
        float a0 = __expf(m0 - mn0), a1 = __expf(m1 - mn1);
        m0 = mn0; m1 = mn1;
        l0 *= a0; l1 *= a1;
        #pragma unroll
        for (int nf = 0; nf < 8; nf++) {
            o[nf][0] *= a0; o[nf][1] *= a0;
            o[nf][2] *= a1; o[nf][3] *= a1;
        }

        uint32_t pah[4][4], pal[4][4];
        float sum0 = 0.f, sum1 = 0.f;
        #pragma unroll
        for (int nf = 0; nf < 8; nf++) {
            float p0 = __expf(s[nf][0] - m0);
            float p1 = __expf(s[nf][1] - m0);
            float p2 = __expf(s[nf][2] - m1);
            float p3 = __expf(s[nf][3] - m1);
            sum0 += p0 + p1; sum1 += p2 + p3;
            int ks = nf >> 1, part = nf & 1;
            split2(p0, p1, pah[ks][2 * part],     pal[ks][2 * part]);
            split2(p2, p3, pah[ks][2 * part + 1], pal[ks][2 * part + 1]);
        }
        sum0 += __shfl_xor_sync(0xffffffffu, sum0, 1);
        sum0 += __shfl_xor_sync(0xffffffffu, sum0, 2);
        sum1 += __shfl_xor_sync(0xffffffffu, sum1, 1);
        sum1 += __shfl_xor_sync(0xffffffffu, sum1, 2);
        l0 += sum0; l1 += sum1;

        #pragma unroll
        for (int ks = 0; ks < 4; ks++) {
            #pragma unroll
            for (int nf = 0; nf < 8; nf++) {
                int d = 8 * nf + q;
                uint32_t bh0 = VpH[8 * ks + r    ][d];
                uint32_t bh1 = VpH[8 * ks + r + 4][d];
                uint32_t bl0 = VpL[8 * ks + r    ][d];
                uint32_t bl1 = VpL[8 * ks + r + 4][d];
                mma_bf16(o[nf], pah[ks], bh0, bh1);
                mma_bf16(o[nf], pal[ks], bh0, bh1);
                mma_bf16(o[nf], pah[ks], bl0, bl1);
            }
        }
    }

    float inv0 = 1.0f / l0, inv1 = 1.0f / l1;
    uint32_t* O0h = outH + (size_t)(b * SEQ + qrow + q) * 512 + 32 * h;
    uint32_t* O0l = outL + (size_t)(b * SEQ + qrow + q) * 512 + 32 * h;
    uint32_t* O1h = O0h + 8 * 512;
    uint32_t* O1l = O0l + 8 * 512;
    #pragma unroll
    for (int nf = 0; nf < 8; nf++) {
        int pc = 4 * nf + r;
        uint32_t hh, ll;
        split2(o[nf][0] * inv0, o[nf][1] * inv0, hh, ll);
        O0h[pc] = hh; O0l[pc] = ll;
        split2(o[nf][2] * inv1, o[nf][3] * inv1, hh, ll);
        O1h[pc] = hh; O1l[pc] = ll;
    }
}

// ---------------------------------------------------------------------------
__global__ __launch_bounds__(256) void geglu_kernel(
    const float* __restrict__ u,
    uint32_t* __restrict__ outH, uint32_t* __restrict__ outL)
{
    int i = blockIdx.x * 256 + threadIdx.x;
    int row = i >> 10;
    int c4  = i & 1023;
    const float4* base = (const float4*)(u + (size_t)row * (2 * FFDIM));
    float4 a = base[c4];
    float4 g = base[c4 + 1024];
    float o0 = a.x * g.x * normcdff(g.x);
    float o1 = a.y * g.y * normcdff(g.y);
    float o2 = a.z * g.z * normcdff(g.z);
    float o3 = a.w * g.w * normcdff(g.w);
    uint32_t h0,l0,h1,l1;
    split2(o0, o1, h0, l0);
    split2(o2, o3, h1, l1);
    ((uint2*)(outH + (size_t)row * 2048))[c4] = make_uint2(h0, h1);
    ((uint2*)(outL + (size_t)row * 2048))[c4] = make_uint2(l0, l1);
}

// ---------------------------------------------------------------------------
extern "C" void kernel_launch(void* const* d_in, const int* in_sizes, int n_in,
                              void* d_out, int out_size)
{
    const float* x            = (const float*)d_in[0];
    const float* w_qkv        = (const float*)d_in[2];
    const float* w_out        = (const float*)d_in[3];
    const float* b_out        = (const float*)d_in[4];
    const float* ln_inner_g   = (const float*)d_in[5];
    const float* ln_inner_b   = (const float*)d_in[6];
    const float* ln_pre_attn_g= (const float*)d_in[7];
    const float* ln_pre_attn_b= (const float*)d_in[8];
    const float* scale_attn   = (const float*)d_in[9];
    const float* w1           = (const float*)d_in[10];
    const float* b1           = (const float*)d_in[11];
    const float* w2           = (const float*)d_in[12];
    const float* b2           = (const float*)d_in[13];
    const float* ln_pre_ff_g  = (const float*)d_in[14];
    const float* ln_pre_ff_b  = (const float*)d_in[15];
    const float* scale_ff     = (const float*)d_in[16];
    float* out = (float*)d_out;

    uint32_t *whP, *wlP, *ahP, *alP, *qhP, *qlP;
    float *uP, *pP;
    cudaGetSymbolAddress((void**)&whP, g_wh);
    cudaGetSymbolAddress((void**)&wlP, g_wl);
    cudaGetSymbolAddress((void**)&ahP, g_ah);
    cudaGetSymbolAddress((void**)&alP, g_al);
    cudaGetSymbolAddress((void**)&qhP, g_qh);
    cudaGetSymbolAddress((void**)&qlP, g_ql);
    cudaGetSymbolAddress((void**)&uP,  g_u);
    cudaGetSymbolAddress((void**)&pP,  g_p);

    cudaFuncSetAttribute(gemm_ps_kernel,
                         cudaFuncAttributeMaxDynamicSharedMemorySize, GSMEM_B);

    // 0) split + transpose weights -> Wt[n][K/2] pair-packed hi/lo
    split_wt_kernel<<<dim3(3072/64, 1024/32), 256>>>(w_qkv, whP + OFF_WQKV, wlP + OFF_WQKV, 3072, 512);
    split_wt_kernel<<<dim3(1024/64, 1024/32), 256>>>(w_out, whP + OFF_WOUT, wlP + OFF_WOUT, 1024, 512);
    split_wt_kernel<<<dim3(8192/64, 1024/32), 256>>>(w1,    whP + OFF_W1,   wlP + OFF_W1,   8192, 512);
    split_wt_kernel<<<dim3(1024/64, 4096/32), 256>>>(w2,    whP + OFF_W2,   wlP + OFF_W2,   1024, 2048);

    // 1) h = LN_pre_attn(x) -> packed
    ln_kernel<<<NTOK, 256>>>(x, ln_pre_attn_g, ln_pre_attn_b, ahP, alP);

    // 2) qkv = h @ w_qkv -> packed (Q cols pre-scaled by 0.125)
    gemm_ps_kernel<<<dim3(3072/128, NTOK/256), 256, GSMEM_B>>>(
        ahP, alP, 512, whP + OFF_WQKV, wlP + OFF_WQKV, 512,
        nullptr, nullptr, nullptr, qhP, qlP, 1024, NTOK, 3072, DMODEL);

    // 3) attention -> packed g_ah/g_al
    attn_tc_kernel<<<dim3(SEQ/128, 2 * NHEAD), 256>>>(qhP, qlP, ahP, alP);

    // 4) proj = attn @ w_out + b_out -> fp32 g_p
    gemm_ps_kernel<<<dim3(DMODEL/128, NTOK/256), 256, GSMEM_B>>>(
        ahP, alP, 512, whP + OFF_WOUT, wlP + OFF_WOUT, 512,
        b_out, nullptr, pP, nullptr, nullptr, 0, NTOK, DMODEL, DMODEL);

    // 5) h2 = LN_pre_ff(LN_inner(p) * scale_attn) -> packed
    dln_kernel<<<NTOK, 256>>>(pP, ln_inner_g, ln_inner_b, scale_attn,
                              ln_pre_ff_g, ln_pre_ff_b, ahP, alP);

    // 6) u = h2 @ w1 + b1 -> fp32 g_u
    gemm_ps_kernel<<<dim3(2*FFDIM/128, NTOK/256), 256, GSMEM_B>>>(
        ahP, alP, 512, whP + OFF_W1, wlP + OFF_W1, 512,
        b1, nullptr, uP, nullptr, nullptr, 0, NTOK, 2 * FFDIM, DMODEL);

    // 7) GeGLU -> packed (row stride 2048 pairs)
    geglu_kernel<<<(NTOK * (FFDIM/4)) / 256, 256>>>(uP, ahP, alP);

    // 8) out = geglu @ w2 + b2, * scale_ff -> d_out
    gemm_ps_kernel<<<dim3(DMODEL/128, NTOK/256), 256, GSMEM_B>>>(
        ahP, alP, 2048, whP + OFF_W2, wlP + OFF_W2, 2048,
        b2, scale_ff, out, nullptr, nullptr, 0, NTOK, DMODEL, FFDIM);
}